// round 2
// baseline (speedup 1.0000x reference)
#include <cuda_runtime.h>

// Problem constants
constexpr int B_ = 8, E_ = 16, H_ = 256, W_ = 256;
constexpr int HW   = H_ * W_;            // 65536
constexpr int NPIX = B_ * HW;            // 524288
constexpr int TPB  = 256;
constexpr int PPT  = 4;                  // pixels per thread (float4)
constexpr int NBLK = NPIX / (TPB * PPT); // 512

// Deterministic fixed-point global accumulator (order-independent integer adds).
__device__ unsigned long long g_acc;   // zero-initialized; reset by last block each run
__device__ unsigned int       g_tick;  // block-completion counter

constexpr double FPSCALE = 4294967296.0;  // 2^32

__global__ void __launch_bounds__(TPB)
crps_fused_kernel(const float* __restrict__ fore, const float* __restrict__ obs,
                  float* __restrict__ out) {
    const int t  = blockIdx.x * TPB + threadIdx.x;   // thread id, handles pixels [4t, 4t+3]
    const int g0 = t * PPT;                          // first pixel id
    const int b  = g0 >> 16;                         // g0 / HW  (HW = 65536, same b for all 4)
    const int p  = g0 & (HW - 1);                    // g0 % HW

    const float* fb = fore + ((size_t)b * E_) * HW + p;

    // Load 16 ensemble members x 4 pixels as float4 (16 x LDG.128, high MLP).
    float4 f4[E_];
#pragma unroll
    for (int e = 0; e < E_; e++)
        f4[e] = *reinterpret_cast<const float4*>(fb + (size_t)e * HW);

    const float4 o4 = *reinterpret_cast<const float4*>(obs + g0);

    float acc = 0.f;

    // Process the 4 pixels sequentially; each frees its registers when done.
#pragma unroll
    for (int c = 0; c < PPT; c++) {
        float f[E_];
        float o;
        if (c == 0) { o = o4.x; }
        else if (c == 1) { o = o4.y; }
        else if (c == 2) { o = o4.z; }
        else { o = o4.w; }
#pragma unroll
        for (int e = 0; e < E_; e++) {
            const float4 v = f4[e];
            f[e] = (c == 0) ? v.x : (c == 1) ? v.y : (c == 2) ? v.z : v.w;
        }

        // term1 numerator: sum_e |f_e - o|
        float s1 = 0.f;
#pragma unroll
        for (int e = 0; e < E_; e++) s1 += fabsf(f[e] - o);

        // Batcher odd-even mergesort network for 16 elements (63 comparators).
#pragma unroll
        for (int pp = 1; pp < E_; pp <<= 1) {
#pragma unroll
            for (int k = pp; k > 0; k >>= 1) {
#pragma unroll
                for (int j = k % pp; j + k < E_; j += 2 * k) {
#pragma unroll
                    for (int i = 0; i < k; i++) {
                        if (i + j + k < E_) {
                            if ((i + j) / (pp * 2) == (i + j + k) / (pp * 2)) {
                                const int a = i + j, d = i + j + k;
                                const float lo = fminf(f[a], f[d]);
                                const float hi = fmaxf(f[a], f[d]);
                                f[a] = lo; f[d] = hi;
                            }
                        }
                    }
                }
            }
        }

        // sum_{e<e'} |f_e - f_{e'}| = sum_i (2i - 15) * f_(i)  (ascending)
        float s2 = 0.f;
#pragma unroll
        for (int i = 0; i < E_; i++)
            s2 = fmaf((float)(2 * i - 15), f[i], s2);

        // per-pixel contribution: term1 - 0.5*term2 = s1/16 - s2/256
        acc += s1 * (1.0f / 16.0f) - s2 * (1.0f / 256.0f);
    }

    // ---- Deterministic block reduction (fixed shuffle tree) ----
    const int lane = threadIdx.x & 31;
    const int wid  = threadIdx.x >> 5;
    float v = acc;
#pragma unroll
    for (int off = 16; off > 0; off >>= 1)
        v += __shfl_down_sync(0xffffffffu, v, off);

    __shared__ float ws[TPB / 32];
    if (lane == 0) ws[wid] = v;
    __syncthreads();

    __shared__ bool is_last;
    if (wid == 0) {
        float x = (lane < TPB / 32) ? ws[lane] : 0.f;
#pragma unroll
        for (int off = 4; off > 0; off >>= 1)
            x += __shfl_down_sync(0xffffffffu, x, off);
        if (lane == 0) {
            // Fixed-point conversion -> order-independent (deterministic) global sum.
            const long long q = __double2ll_rn((double)x * FPSCALE);
            atomicAdd(&g_acc, (unsigned long long)q);
            __threadfence();
            const unsigned int tk = atomicAdd(&g_tick, 1u);
            is_last = (tk == (unsigned int)(gridDim.x - 1));
        }
    }
    __syncthreads();

    if (threadIdx.x == 0 && is_last) {
        const unsigned long long tot = atomicAdd(&g_acc, 0ull);  // atomic read
        const double s = (double)(long long)tot / FPSCALE;
        out[0] = (float)(s / (double)NPIX);
        // Reset for next graph replay.
        g_acc  = 0ull;
        g_tick = 0u;
        __threadfence();
    }
}

extern "C" void kernel_launch(void* const* d_in, const int* in_sizes, int n_in,
                              void* d_out, int out_size) {
    const float* fore = (const float*)d_in[0];
    const float* obs  = (const float*)d_in[1];
    float* out = (float*)d_out;

    crps_fused_kernel<<<NBLK, TPB>>>(fore, obs, out);
}

// round 3
// speedup vs baseline: 1.4719x; 1.4719x over previous
#include <cuda_runtime.h>

// Problem constants
constexpr int B_ = 8, E_ = 16, H_ = 256, W_ = 256;
constexpr int HW   = H_ * W_;            // 65536
constexpr int NPIX = B_ * HW;            // 524288
constexpr int TPB  = 256;
constexpr int PPT  = 2;                  // pixels per thread (float2 loads)
constexpr int NBLK = NPIX / (TPB * PPT); // 1024

// Deterministic fixed-point global accumulator (order-independent integer adds).
__device__ unsigned long long g_acc;   // zeroed at start; reset by last block each run
__device__ unsigned int       g_tick;  // block-completion counter

constexpr double FPSCALE = 4294967296.0;  // 2^32

__global__ void __launch_bounds__(TPB, 4)
crps_fused_kernel(const float* __restrict__ fore, const float* __restrict__ obs,
                  float* __restrict__ out) {
    const int t  = blockIdx.x * TPB + threadIdx.x;   // thread id
    const int g0 = t * PPT;                          // first pixel id
    const int b  = g0 >> 16;                         // g0 / HW (same b for both pixels)
    const int p  = g0 & (HW - 1);                    // g0 % HW

    const float* fb = fore + ((size_t)b * E_) * HW + p;

    // 16 ensemble members x 2 pixels as float2 (16 x LDG.64, MLP=16).
    float2 f2[E_];
#pragma unroll
    for (int e = 0; e < E_; e++)
        f2[e] = *reinterpret_cast<const float2*>(fb + (size_t)e * HW);

    const float2 o2 = *reinterpret_cast<const float2*>(obs + g0);

    float acc = 0.f;

#pragma unroll
    for (int c = 0; c < PPT; c++) {
        const float o = (c == 0) ? o2.x : o2.y;
        float f[E_];
#pragma unroll
        for (int e = 0; e < E_; e++)
            f[e] = (c == 0) ? f2[e].x : f2[e].y;

        // term1 numerator: sum_e |f_e - o|   (fma pipe)
        float s1 = 0.f;
#pragma unroll
        for (int e = 0; e < E_; e++) s1 += fabsf(f[e] - o);

        // Batcher odd-even mergesort, 16 elems, 63 FMNMX pairs (alu pipe).
#pragma unroll
        for (int pp = 1; pp < E_; pp <<= 1) {
#pragma unroll
            for (int k = pp; k > 0; k >>= 1) {
#pragma unroll
                for (int j = k % pp; j + k < E_; j += 2 * k) {
#pragma unroll
                    for (int i = 0; i < k; i++) {
                        if (i + j + k < E_) {
                            if ((i + j) / (pp * 2) == (i + j + k) / (pp * 2)) {
                                const int a = i + j, d = i + j + k;
                                const float lo = fminf(f[a], f[d]);
                                const float hi = fmaxf(f[a], f[d]);
                                f[a] = lo; f[d] = hi;
                            }
                        }
                    }
                }
            }
        }

        // sum_{e<e'} |f_e - f_{e'}| = sum_i (2i - 15) * f_(i)  (ascending)
        float s2 = 0.f;
#pragma unroll
        for (int i = 0; i < E_; i++)
            s2 = fmaf((float)(2 * i - 15), f[i], s2);

        // per-pixel: term1 - 0.5*term2 = s1/16 - s2/256
        acc += s1 * (1.0f / 16.0f) - s2 * (1.0f / 256.0f);
    }

    // ---- Deterministic in-kernel reduction ----
    const int lane = threadIdx.x & 31;
    const int wid  = threadIdx.x >> 5;
    float v = acc;
#pragma unroll
    for (int off = 16; off > 0; off >>= 1)
        v += __shfl_down_sync(0xffffffffu, v, off);

    __shared__ float ws[TPB / 32];
    if (lane == 0) ws[wid] = v;
    __syncthreads();

    __shared__ bool is_last;
    if (wid == 0) {
        float x = (lane < TPB / 32) ? ws[lane] : 0.f;
#pragma unroll
        for (int off = 4; off > 0; off >>= 1)
            x += __shfl_down_sync(0xffffffffu, x, off);
        if (lane == 0) {
            // Fixed-point -> order-independent (deterministic) global sum.
            const long long q = __double2ll_rn((double)x * FPSCALE);
            atomicAdd(&g_acc, (unsigned long long)q);
            __threadfence();
            const unsigned int tk = atomicAdd(&g_tick, 1u);
            is_last = (tk == (unsigned int)(gridDim.x - 1));
        }
    }
    __syncthreads();

    if (threadIdx.x == 0 && is_last) {
        const unsigned long long tot = atomicAdd(&g_acc, 0ull);  // atomic read
        const double s = (double)(long long)tot / FPSCALE;
        out[0] = (float)(s / (double)NPIX);
        // Reset for next graph replay.
        g_acc  = 0ull;
        g_tick = 0u;
        __threadfence();
    }
}

extern "C" void kernel_launch(void* const* d_in, const int* in_sizes, int n_in,
                              void* d_out, int out_size) {
    const float* fore = (const float*)d_in[0];
    const float* obs  = (const float*)d_in[1];
    float* out = (float*)d_out;

    crps_fused_kernel<<<NBLK, TPB>>>(fore, obs, out);
}

// round 5
// speedup vs baseline: 2.8850x; 1.9600x over previous
#include <cuda_runtime.h>

// Problem constants
constexpr int B_ = 8, E_ = 16, H_ = 256, W_ = 256;
constexpr int HW   = H_ * W_;        // 65536
constexpr int NPIX = B_ * HW;        // 524288
constexpr int TPB  = 256;
constexpr int NBLK = NPIX / TPB;     // 2048

// Deterministic fixed-point global accumulator (order-independent integer adds).
__device__ unsigned long long g_acc;   // zeroed at load; reset by last block each run
__device__ unsigned int       g_tick;  // block-completion counter

constexpr double FPSCALE = 4294967296.0;  // 2^32

__global__ void __launch_bounds__(TPB, 6)
crps_fused_kernel(const float* __restrict__ fore, const float* __restrict__ obs,
                  float* __restrict__ out) {
    const int g = blockIdx.x * TPB + threadIdx.x;   // pixel id
    const int b = g >> 16;                          // g / HW
    const int p = g & (HW - 1);                     // g % HW

    const float* fb = fore + ((size_t)b * E_) * HW + p;

    // 16 scalar loads with compile-time immediate offsets (e*HW*4B = 256KB each,
    // fits LDG's 24-bit immediate). Front-batched -> MLP=16 per thread.
    float f[E_];
#pragma unroll
    for (int e = 0; e < E_; e++) f[e] = __ldg(fb + e * HW);

    const float o = __ldg(obs + g);

    // term1 numerator: sum_e |f_e - o|   (fma pipe)
    float s1 = 0.f;
#pragma unroll
    for (int e = 0; e < E_; e++) s1 += fabsf(f[e] - o);

    // Batcher odd-even mergesort, 16 elems, 63 comparators (126 FMNMX, alu pipe).
#pragma unroll
    for (int pp = 1; pp < E_; pp <<= 1) {
#pragma unroll
        for (int k = pp; k > 0; k >>= 1) {
#pragma unroll
            for (int j = k % pp; j + k < E_; j += 2 * k) {
#pragma unroll
                for (int i = 0; i < k; i++) {
                    if (i + j + k < E_) {
                        if ((i + j) / (pp * 2) == (i + j + k) / (pp * 2)) {
                            const int a = i + j, d = i + j + k;
                            const float lo = fminf(f[a], f[d]);
                            const float hi = fmaxf(f[a], f[d]);
                            f[a] = lo; f[d] = hi;
                        }
                    }
                }
            }
        }
    }

    // sum_{e<e'} |f_e - f_{e'}| = sum_i (2i - 15) * f_(i)  (ascending)
    float s2 = 0.f;
#pragma unroll
    for (int i = 0; i < E_; i++)
        s2 = fmaf((float)(2 * i - 15), f[i], s2);

    // per-pixel contribution: term1 - 0.5*term2 = s1/16 - s2/256
    const float val = s1 * (1.0f / 16.0f) - s2 * (1.0f / 256.0f);

    // ---- Deterministic in-kernel reduction ----
    const int lane = threadIdx.x & 31;
    const int wid  = threadIdx.x >> 5;
    float v = val;
#pragma unroll
    for (int off = 16; off > 0; off >>= 1)
        v += __shfl_down_sync(0xffffffffu, v, off);

    __shared__ float ws[TPB / 32];
    if (lane == 0) ws[wid] = v;
    __syncthreads();

    __shared__ bool is_last;
    if (wid == 0) {
        float x = (lane < TPB / 32) ? ws[lane] : 0.f;
#pragma unroll
        for (int off = 4; off > 0; off >>= 1)
            x += __shfl_down_sync(0xffffffffu, x, off);
        if (lane == 0) {
            // Fixed-point -> order-independent (deterministic) global sum.
            const long long q = __double2ll_rn((double)x * FPSCALE);
            atomicAdd(&g_acc, (unsigned long long)q);
            __threadfence();
            const unsigned int tk = atomicAdd(&g_tick, 1u);
            is_last = (tk == (unsigned int)(gridDim.x - 1));
        }
    }
    __syncthreads();

    if (threadIdx.x == 0 && is_last) {
        const unsigned long long tot = atomicAdd(&g_acc, 0ull);  // atomic read
        const double s = (double)(long long)tot / FPSCALE;
        out[0] = (float)(s / (double)NPIX);
        // Reset for next graph replay.
        g_acc  = 0ull;
        g_tick = 0u;
        __threadfence();
    }
}

extern "C" void kernel_launch(void* const* d_in, const int* in_sizes, int n_in,
                              void* d_out, int out_size) {
    const float* fore = (const float*)d_in[0];
    const float* obs  = (const float*)d_in[1];
    float* out = (float*)d_out;

    crps_fused_kernel<<<NBLK, TPB>>>(fore, obs, out);
}